// round 11
// baseline (speedup 1.0000x reference)
#include <cuda_runtime.h>
#include <cuda_bf16.h>
#include <cstdint>

// Sobel gradient magnitude, zero-padded, on [B=8, C=64, H=256, W=256] fp32.
// out = sqrt(gv^2 + gh^2 + 1e-6), gv = x[i+1,j]-x[i-1,j], gh = x[i,j+1]-x[i,j-1].
//
// Round 11: full-row warps. Each thread handles TWO column strips (col4 = lane
// and lane+32) x 4 rows with the rolling 3-vector window, so one warp covers a
// complete 256-float row. ALL horizontal neighbors come from shuffles:
//   - lane-0 left / lane-31 right are true zero-pad edges (no loads),
//   - the strip seam is bridged with shfl(b.x, 0) / shfl(a.w, 31).
// This eliminates every predicated scalar edge load and divergent branch from
// the hot loop while keeping both LDG.128 streams perfectly coalesced.
// Write-back stores (R10 win), IEEE sqrtf (approx was wall-neutral-negative).
//
// Layout: W4 = 64 float4 per row, plane = 2^14 float4.
// Thread t: lane strip col4 = {lane, lane+32}, rq = (t>>5) & 63, plane = t>>11.

static constexpr int W4 = 64;

__global__ __launch_bounds__(256, 6)
void sobel_grad_mag_r11(const float4* __restrict__ in,
                        float4* __restrict__ out)
{
    const int t    = blockIdx.x * blockDim.x + threadIdx.x;
    const int lane = threadIdx.x & 31;
    const int rq   = (t >> 5) & 63;                  // rows 4*rq .. 4*rq+3
    const int ia   = ((t >> 11) << 14) | (rq << 8) | lane;   // strip A: col4 = lane
    const int ib   = ia + 32;                                // strip B: col4 = lane+32

    const float4 zero = make_float4(0.f, 0.f, 0.f, 0.f);
    const float EPS = 1e-6f;
    const bool top = (rq == 0);
    const bool bot = (rq == 63);

    // rolling windows for both strips; prologue front-issues 6 loads
    float4 upA = top ? zero : __ldg(&in[ia - W4]);
    float4 upB = top ? zero : __ldg(&in[ib - W4]);
    float4 cA  = __ldg(&in[ia]);
    float4 cB  = __ldg(&in[ib]);
    float4 dnA = __ldg(&in[ia + W4]);
    float4 dnB = __ldg(&in[ib + W4]);

    #pragma unroll
    for (int k = 0; k < 4; k++) {
        float4 nxA, nxB;
        if (k < 3) {
            if (k == 2 && bot) {
                nxA = zero; nxB = zero;
            } else {
                nxA = __ldg(&in[ia + (k + 2) * W4]);
                nxB = __ldg(&in[ib + (k + 2) * W4]);
            }
        }

        // horizontal neighbors, all via shuffle (warp spans the full row)
        float lA = __shfl_up_sync(0xffffffffu, cA.w, 1);     // lane0 -> zero pad
        float rB = __shfl_down_sync(0xffffffffu, cB.x, 1);   // lane31 -> zero pad
        float seamL = __shfl_sync(0xffffffffu, cA.w, 31);    // a.w of lane 31
        float seamR = __shfl_sync(0xffffffffu, cB.x, 0);     // b.x of lane 0
        float rA = __shfl_down_sync(0xffffffffu, cA.x, 1);
        float lB = __shfl_up_sync(0xffffffffu, cB.w, 1);
        if (lane == 0)  { lA = 0.f; lB = seamL; }
        if (lane == 31) { rA = seamR; rB = 0.f; }

        // strip A
        {
            const float gv0 = dnA.x - upA.x;
            const float gv1 = dnA.y - upA.y;
            const float gv2 = dnA.z - upA.z;
            const float gv3 = dnA.w - upA.w;
            const float gh0 = cA.y - lA;
            const float gh1 = cA.z - cA.x;
            const float gh2 = cA.w - cA.y;
            const float gh3 = rA   - cA.z;
            float4 res;
            res.x = sqrtf(fmaf(gv0, gv0, fmaf(gh0, gh0, EPS)));
            res.y = sqrtf(fmaf(gv1, gv1, fmaf(gh1, gh1, EPS)));
            res.z = sqrtf(fmaf(gv2, gv2, fmaf(gh2, gh2, EPS)));
            res.w = sqrtf(fmaf(gv3, gv3, fmaf(gh3, gh3, EPS)));
            out[ia + k * W4] = res;
        }

        // strip B
        {
            const float gv0 = dnB.x - upB.x;
            const float gv1 = dnB.y - upB.y;
            const float gv2 = dnB.z - upB.z;
            const float gv3 = dnB.w - upB.w;
            const float gh0 = cB.y - lB;
            const float gh1 = cB.z - cB.x;
            const float gh2 = cB.w - cB.y;
            const float gh3 = rB   - cB.z;
            float4 res;
            res.x = sqrtf(fmaf(gv0, gv0, fmaf(gh0, gh0, EPS)));
            res.y = sqrtf(fmaf(gv1, gv1, fmaf(gh1, gh1, EPS)));
            res.z = sqrtf(fmaf(gv2, gv2, fmaf(gh2, gh2, EPS)));
            res.w = sqrtf(fmaf(gv3, gv3, fmaf(gh3, gh3, EPS)));
            out[ib + k * W4] = res;
        }

        // rotate windows
        upA = cA; cA = dnA;
        upB = cB; cB = dnB;
        if (k < 3) { dnA = nxA; dnB = nxB; }
    }
}

extern "C" void kernel_launch(void* const* d_in, const int* in_sizes, int n_in,
                              void* d_out, int out_size)
{
    const float4* x = reinterpret_cast<const float4*>(d_in[0]);
    float4* o       = reinterpret_cast<float4*>(d_out);

    // each thread produces 8 float4 (4 rows x 2 strips)
    int nthreads = out_size / 32;   // 1,048,576 (exactly 4096 * 256)
    int threads  = 256;
    int blocks   = nthreads / threads;

    sobel_grad_mag_r11<<<blocks, threads>>>(x, o);
}

// round 12
// speedup vs baseline: 1.0654x; 1.0654x over previous
#include <cuda_runtime.h>
#include <cuda_bf16.h>
#include <cstdint>

// Sobel gradient magnitude, zero-padded, on [B=8, C=64, H=256, W=256] fp32.
// out = sqrt(gv^2 + gh^2 + 1e-6), gv = x[i+1,j]-x[i-1,j], gh = x[i,j+1]-x[i,j-1].
//
// FINAL (R10 confirmed): 512-thread blocks, 4 rows/thread with a rolling
// 3-vector register window, warp-shuffle horizontal neighbors with predicated
// lane-0/31 edge loads, default write-back stores, IEEE sqrtf, exact grid.
//
// Measured landscape (ncu dur / DRAM%):
//   this kernel:        36.5us / 73.8%  <- best
//   streaming stores:   36.9us / 72.6%  (R/W turnaround penalty)
//   8-row blocking:     38.4us / 70.7%  (longer dep chains, fewer warps/work)
//   persistent grid:    44.7us / 62.2%  (serialized memory issue)
//   2-strip full-row:   42.2us / 67.4%  (reg pressure, L1 wavefront inflation)
// 256 MB mandatory traffic at ~5.85 TB/s effective = mixed-R/W HBM3e plateau.
//
// Layout: W4 = 64 float4 per row, H = 256 rows, plane = 2^14 float4.

static constexpr int W4 = 64;

__global__ __launch_bounds__(512, 4)
void sobel_grad_mag_final(const float4* __restrict__ in,
                          float4* __restrict__ out)
{
    const int t = blockIdx.x * blockDim.x + threadIdx.x;

    const int lane = threadIdx.x & 31;
    const int col4 = t & (W4 - 1);
    const int rq   = (t >> 6) & 63;                 // rows 4*rq .. 4*rq+3
    const int i0   = ((t >> 12) << 14) | (rq << 8) | col4;

    const float4 zero = make_float4(0.f, 0.f, 0.f, 0.f);
    const float* sc = reinterpret_cast<const float*>(in);
    const float EPS = 1e-6f;
    const bool need_l = (lane == 0)  && (col4 != 0);
    const bool need_r = (lane == 31) && (col4 != W4 - 1);

    // prologue: 4 front-issued loads (up, c, dn, first nxt)
    float4 up  = (rq == 0) ? zero : __ldg(&in[i0 - W4]);
    float4 c   = __ldg(&in[i0]);
    float4 dn  = __ldg(&in[i0 + W4]);
    float4 nx0 = __ldg(&in[i0 + 2 * W4]);

    #pragma unroll
    for (int k = 0; k < 4; k++) {
        float4 nxt;
        if (k == 0) {
            nxt = nx0;
        } else if (k < 3) {
            nxt = (k == 2 && rq == 63) ? zero : __ldg(&in[i0 + (k + 2) * W4]);
        }

        // horizontal neighbors from adjacent lanes (same row vector)
        float l = __shfl_up_sync(0xffffffffu, c.w, 1);
        float r = __shfl_down_sync(0xffffffffu, c.x, 1);
        if (lane == 0)
            l = need_l ? sc[(size_t)(i0 + k * W4) * 4 - 1] : 0.f;
        if (lane == 31)
            r = need_r ? sc[(size_t)(i0 + k * W4) * 4 + 4] : 0.f;

        const float gv0 = dn.x - up.x;
        const float gv1 = dn.y - up.y;
        const float gv2 = dn.z - up.z;
        const float gv3 = dn.w - up.w;

        const float gh0 = c.y - l;
        const float gh1 = c.z - c.x;
        const float gh2 = c.w - c.y;
        const float gh3 = r   - c.z;

        float4 res;
        res.x = sqrtf(fmaf(gv0, gv0, fmaf(gh0, gh0, EPS)));
        res.y = sqrtf(fmaf(gv1, gv1, fmaf(gh1, gh1, EPS)));
        res.z = sqrtf(fmaf(gv2, gv2, fmaf(gh2, gh2, EPS)));
        res.w = sqrtf(fmaf(gv3, gv3, fmaf(gh3, gh3, EPS)));

        out[i0 + k * W4] = res;   // write-back store (measured best)

        // rotate window
        up = c;
        c  = dn;
        if (k < 3) dn = nxt;
    }
}

extern "C" void kernel_launch(void* const* d_in, const int* in_sizes, int n_in,
                              void* d_out, int out_size)
{
    const float4* x = reinterpret_cast<const float4*>(d_in[0]);
    float4* o       = reinterpret_cast<float4*>(d_out);

    // total float4 outputs = out_size/4; each thread produces 4 of them
    int nthreads = out_size / 16;   // 2,097,152 (exactly 4096 * 512)
    int threads  = 512;
    int blocks   = nthreads / threads;

    sobel_grad_mag_final<<<blocks, threads>>>(x, o);
}